// round 6
// baseline (speedup 1.0000x reference)
#include <cuda_runtime.h>
#include <cuda_bf16.h>
#include <cstdint>

#define D 64
#define MAX_NODES 100000

// scratch (no cudaMalloc allowed): bf16 neighbor sums + bf16 copy of emb.
__device__ __align__(16) __nv_bfloat16 g_nbr[(size_t)MAX_NODES * D];
__device__ __align__(16) __nv_bfloat16 g_embh[(size_t)MAX_NODES * D];

static __device__ __forceinline__ uint32_t pack_bf2(float a, float b) {
    uint32_t r;
    asm("cvt.rn.bf16x2.f32 %0, %1, %2;" : "=r"(r) : "f"(b), "f"(a));  // lo=a, hi=b
    return r;
}

// ---------------------------------------------------------------------------
// Kernel 1: prep — convert emb fp32 -> bf16 scratch, zero g_nbr, zero d_out.
// ---------------------------------------------------------------------------
__global__ __launch_bounds__(256) void prep_kernel(const float* __restrict__ emb,
                                                   float* __restrict__ out,
                                                   int n_grp) {
    int i = blockIdx.x * blockDim.x + threadIdx.x;
    if (i < n_grp) {
        float4 v = __ldg(reinterpret_cast<const float4*>(emb) + i);
        uint2 pk;
        pk.x = pack_bf2(v.x, v.y);
        pk.y = pack_bf2(v.z, v.w);
        reinterpret_cast<uint2*>(g_embh)[i] = pk;
        reinterpret_cast<uint2*>(g_nbr)[i] = make_uint2(0u, 0u);
    }
    if (i < D / 4) reinterpret_cast<float4*>(out)[i] = make_float4(0.f, 0.f, 0.f, 0.f);
}

// ---------------------------------------------------------------------------
// Kernel 2: edge scatter  nbr[dst] += emb_bf16[src]   (8 lanes/edge, RED.128)
// ---------------------------------------------------------------------------
#define SCAT_BLOCKS 4736

__global__ __launch_bounds__(256) void scatter_kernel(
    const int* __restrict__ src,
    const int* __restrict__ dst,
    int n_items) {
    int stride = gridDim.x * blockDim.x;
    for (int i = blockIdx.x * blockDim.x + threadIdx.x; i < n_items; i += stride) {
        int e = i >> 3;
        int c = i & 7;
        int s = __ldg(src + e);
        int d = __ldg(dst + e);
        uint4 v = *(reinterpret_cast<const uint4*>(g_embh) + (size_t)s * 8 + c);
        __nv_bfloat16* p = g_nbr + (size_t)d * D + c * 8;
        asm volatile("red.global.add.noftz.v4.bf16x2 [%0], {%1,%2,%3,%4};"
                     :: "l"(p), "r"(v.x), "r"(v.y), "r"(v.z), "r"(v.w)
                     : "memory");
    }
}

// ---------------------------------------------------------------------------
// Kernel 3: fused MLP + relu + graph-sum, packed f32x2 FMA.
//   out += sum_v relu(feat[v] @ W1^T + b1 + nbr[v] @ W2^T + b2)
// 256 threads = 64 outputs x 4 node-groups. Each thread owns ONE output o:
// W1[o][:] and W2[o][:] live in 64 u64 registers (k-pairs, packed f32x2),
// loaded once. Per tile of 64 nodes staged in smem, each thread walks its
// group's 16 nodes: activation row read as broadcast LDS.128 (k-contiguous,
// matching the k-packed weights — no transpose, no splats), two independent
// packed accumulator chains (feat*W1, nbr*W2), halves summed at the end.
// ---------------------------------------------------------------------------
#define FMA2(acc, a, b) \
    asm("fma.rn.f32x2 %0, %1, %2, %0;" : "+l"(acc) : "l"(a), "l"(b))

#define MLP_BLOCKS 148

__global__ __launch_bounds__(256, 1) void mlp_kernel(
    const float* __restrict__ feat,
    const float* __restrict__ W1,
    const float* __restrict__ b1,
    const float* __restrict__ W2,
    const float* __restrict__ b2,
    float* __restrict__ out,
    int n_nodes) {

    __shared__ float fS[64][D];       // 16KB, [node][k]
    __shared__ float nS[64][D];       // 16KB
    __shared__ float redbuf[4][D];    // 1KB

    const int t   = threadIdx.x;
    const int o   = t & 63;           // this thread's output column
    const int grp = t >> 6;           // node group 0..3 (16 nodes each)

    // weights for output o -> registers, packed as k-pairs (layout already [o][k])
    uint64_t w1r[32], w2r[32];
    {
        const ulonglong2* p1 = reinterpret_cast<const ulonglong2*>(W1 + o * D);
        const ulonglong2* p2 = reinterpret_cast<const ulonglong2*>(W2 + o * D);
        #pragma unroll
        for (int j = 0; j < 16; j++) {
            ulonglong2 a = __ldg(p1 + j);
            ulonglong2 b = __ldg(p2 + j);
            w1r[j * 2] = a.x; w1r[j * 2 + 1] = a.y;
            w2r[j * 2] = b.x; w2r[j * 2 + 1] = b.y;
        }
    }
    const float bc = __ldg(b1 + o) + __ldg(b2 + o);

    float gsum = 0.f;
    const int n_tiles = (n_nodes + 63) >> 6;

    for (int tile = blockIdx.x; tile < n_tiles; tile += gridDim.x) {
        const int base = tile << 6;
        __syncthreads();
        // stage feat: 64 rows x 16 float4
        #pragma unroll
        for (int j = 0; j < 4; j++) {
            int idx = t + j * 256;
            int row = idx >> 4;
            int v = base + row;
            float4 val = (v < n_nodes)
                ? __ldg(reinterpret_cast<const float4*>(feat) + (size_t)v * 16 + (idx & 15))
                : make_float4(0.f, 0.f, 0.f, 0.f);
            reinterpret_cast<float4*>(&fS[0][0])[idx] = val;
        }
        // stage nbr bf16 -> fp32 (exact: bf16 bits << 16)
        #pragma unroll
        for (int j = 0; j < 2; j++) {
            int p = t + j * 256;
            int row = p >> 3;
            int v = base + row;
            uint4 u = (v < n_nodes)
                ? *(reinterpret_cast<const uint4*>(g_nbr) + (size_t)v * 8 + (p & 7))
                : make_uint4(0u, 0u, 0u, 0u);
            float4 lo, hi;
            lo.x = __uint_as_float(u.x << 16); lo.y = __uint_as_float(u.x & 0xffff0000u);
            lo.z = __uint_as_float(u.y << 16); lo.w = __uint_as_float(u.y & 0xffff0000u);
            hi.x = __uint_as_float(u.z << 16); hi.y = __uint_as_float(u.z & 0xffff0000u);
            hi.z = __uint_as_float(u.w << 16); hi.w = __uint_as_float(u.w & 0xffff0000u);
            reinterpret_cast<float4*>(&nS[0][0])[p * 2 + 0] = lo;
            reinterpret_cast<float4*>(&nS[0][0])[p * 2 + 1] = hi;
        }
        __syncthreads();

        const int nlim = n_nodes - base;   // rows < nlim are valid
        #pragma unroll 2
        for (int nn = 0; nn < 16; nn++) {
            const int row = grp * 16 + nn;
            if (row >= nlim) break;
            const ulonglong2* frow = reinterpret_cast<const ulonglong2*>(&fS[row][0]);
            const ulonglong2* nrow = reinterpret_cast<const ulonglong2*>(&nS[row][0]);
            uint64_t accA = 0ull;   // packed (0.f, 0.f)
            uint64_t accB = 0ull;
            #pragma unroll
            for (int j = 0; j < 16; j++) {
                ulonglong2 f4 = frow[j];
                ulonglong2 n4 = nrow[j];
                FMA2(accA, f4.x, w1r[j * 2]);
                FMA2(accB, n4.x, w2r[j * 2]);
                FMA2(accA, f4.y, w1r[j * 2 + 1]);
                FMA2(accB, n4.y, w2r[j * 2 + 1]);
            }
            float alo = __uint_as_float((uint32_t)accA);
            float ahi = __uint_as_float((uint32_t)(accA >> 32));
            float blo = __uint_as_float((uint32_t)accB);
            float bhi = __uint_as_float((uint32_t)(accB >> 32));
            float v = (alo + ahi) + (blo + bhi) + bc;
            gsum += fmaxf(v, 0.f);
        }
    }

    // block reduction: 4 groups -> 1, then atomic into d_out
    __syncthreads();
    redbuf[grp][o] = gsum;
    __syncthreads();
    if (t < D) {
        atomicAdd(out + t, redbuf[0][t] + redbuf[1][t] + redbuf[2][t] + redbuf[3][t]);
    }
}

// ---------------------------------------------------------------------------
// launch — inputs (metadata order): feat, emb, W1, b1, W2, b2, edge_src, edge_dst
// ---------------------------------------------------------------------------
extern "C" void kernel_launch(void* const* d_in, const int* in_sizes, int n_in,
                              void* d_out, int out_size) {
    (void)n_in; (void)out_size;
    const float* feat = (const float*)d_in[0];
    const float* emb  = (const float*)d_in[1];
    const float* W1   = (const float*)d_in[2];
    const float* b1   = (const float*)d_in[3];
    const float* W2   = (const float*)d_in[4];
    const float* b2   = (const float*)d_in[5];
    const int* esrc   = (const int*)d_in[6];
    const int* edst   = (const int*)d_in[7];
    float* out        = (float*)d_out;

    const int n_nodes = in_sizes[0] / D;
    const int n_edges = in_sizes[6];

    // 1) prep: emb->bf16, zero scratch + out
    {
        int n_grp = n_nodes * (D / 4);
        int blocks = (n_grp + 255) / 256;
        prep_kernel<<<blocks, 256>>>(emb, out, n_grp);
    }
    // 2) scatter (bf16 RED.128)
    {
        int n_items = n_edges * 8;
        scatter_kernel<<<SCAT_BLOCKS, 256>>>(esrc, edst, n_items);
    }
    // 3) MLP + relu + graph reduce (packed f32x2)
    mlp_kernel<<<MLP_BLOCKS, 256>>>(feat, W1, b1, W2, b2, out, n_nodes);
}